// round 1
// baseline (speedup 1.0000x reference)
#include <cuda_runtime.h>

// Problem constants
#define BB    8
#define TT    2048
#define CIN   7
#define CC    8
#define NCH   128      // chunks per batch
#define CHK   16       // steps per chunk
#define SIZE  4680     // 8 + 64 + 512 + 4096
#define STRIDE 4736    // padded row stride (floats), 128B multiple
#define O2    8
#define O3    72
#define O4    584
#define HDIM  256

// Scratch (device globals -- no runtime allocation)
__device__ float g_bufA[(size_t)BB * NCH * STRIDE];
__device__ float g_bufB[(size_t)BB * NCH * STRIDE];
__device__ float g_pool[BB * SIZE];
__device__ float g_h[BB * HDIM];

// ---------------------------------------------------------------------------
// Kernel 1: per-chunk signature via Chen iteration of exp(d_s) factors.
// carry levels stored flat in smem: L1 [0,8), L2 [8,72), L3 [72,584), L4 [584,4680)
// ---------------------------------------------------------------------------
__global__ void __launch_bounds__(256) k_chunksig(const float* __restrict__ x)
{
    int blk = blockIdx.x;          // b*NCH + n
    int b = blk >> 7, n = blk & 127;
    int tid = threadIdx.x;

    __shared__ float d[CHK][CC];
    __shared__ float c[SIZE];

    // increments for this chunk (incl. time channel); basepoint zero at t==0
    if (tid < CHK * CC) {
        int s = tid >> 3, ch = tid & 7;
        int t = n * CHK + s;
        float v;
        if (ch < CIN) {
            float cur  = x[(b * TT + t) * CIN + ch];
            float prev = (t > 0) ? x[(b * TT + t - 1) * CIN + ch] : 0.0f;
            v = cur - prev;
        } else {
            v = (t > 0) ? (1.0f / 2047.0f) : 0.0f;
        }
        d[s][ch] = v;
    }
    __syncthreads();

    // init carry = exp_l1(d[0]):  L_k = d^(x)k / k!
    for (int p = tid; p < 4096; p += 256) {
        int i = p >> 9, j = (p >> 6) & 7, k = (p >> 3) & 7, l = p & 7;
        c[O4 + p] = d[0][i] * d[0][j] * d[0][k] * d[0][l] * (1.0f / 24.0f);
    }
    for (int q = tid; q < 512; q += 256) {
        int i = q >> 6, j = (q >> 3) & 7, k = q & 7;
        c[O3 + q] = d[0][i] * d[0][j] * d[0][k] * (1.0f / 6.0f);
    }
    if (tid < 64) { int i = tid >> 3, j = tid & 7; c[O2 + tid] = d[0][i] * d[0][j] * 0.5f; }
    if (tid < 8)  c[tid] = d[0][tid];

    // Chen: carry = carry (x) exp_l1(d_s); in-place top-down (L4 uses old L1..L3)
    for (int s = 1; s < CHK; s++) {
        __syncthreads();
        for (int p = tid; p < 4096; p += 256) {
            int i = p >> 9, j = (p >> 6) & 7, k = (p >> 3) & 7, l = p & 7;
            float dl = d[s][l];
            float dkl = d[s][k] * dl;
            float djkl = d[s][j] * dkl;
            float dijkl = d[s][i] * djkl;
            c[O4 + p] += c[O3 + (p >> 3)] * dl
                       + c[O2 + (p >> 6)] * (dkl * 0.5f)
                       + c[p >> 9]        * (djkl * (1.0f / 6.0f))
                       + dijkl * (1.0f / 24.0f);
        }
        __syncthreads();
        for (int q = tid; q < 512; q += 256) {
            int i = q >> 6, j = (q >> 3) & 7, k = q & 7;
            float dk = d[s][k];
            float djk = d[s][j] * dk;
            float dijk = d[s][i] * djk;
            c[O3 + q] += c[O2 + (q >> 3)] * dk
                       + c[q >> 6] * (djk * 0.5f)
                       + dijk * (1.0f / 6.0f);
        }
        __syncthreads();
        if (tid < 64) {
            int i = tid >> 3, j = tid & 7;
            c[O2 + tid] += c[i] * d[s][j] + d[s][i] * d[s][j] * 0.5f;
        }
        __syncthreads();
        if (tid < 8) c[tid] += d[s][tid];
    }
    __syncthreads();

    float* o = g_bufA + (size_t)blk * STRIDE;
    for (int t = tid; t < SIZE; t += 256) o[t] = c[t];
}

// ---------------------------------------------------------------------------
// Kernel 2: one Hillis-Steele round with the (associative) group product:
//   out[b,n] = (n >= d) ? in[b,n-d] (x) in[b,n] : in[b,n]
// dir==0: A->B ; dir==1: B->A
// ---------------------------------------------------------------------------
__global__ void __launch_bounds__(256) k_scan(int dstep, int dir)
{
    const float* in  = dir ? g_bufB : g_bufA;
    float*       out = dir ? g_bufA : g_bufB;

    int blk = blockIdx.x;
    int n = blk & 127;
    int tid = threadIdx.x;

    const float* Bp = in  + (size_t)blk * STRIDE;
    float*       Op = out + (size_t)blk * STRIDE;

    if (n < dstep) {
        for (int t = tid; t < SIZE; t += 256) Op[t] = Bp[t];
        return;
    }
    const float* Ap = in + (size_t)(blk - dstep) * STRIDE;

    __shared__ float a[O4], bs[O4];   // levels 1..3 of both operands
    for (int t = tid; t < O4; t += 256) { a[t] = Ap[t]; bs[t] = Bp[t]; }
    __syncthreads();

    for (int t = tid; t < SIZE; t += 256) {
        float r;
        if (t >= O4) {
            int p = t - O4;
            r = Ap[t] + Bp[t]
              + a[p >> 9]          * bs[O3 + (p & 511)]
              + a[O2 + (p >> 6)]   * bs[O2 + (p & 63)]
              + a[O3 + (p >> 3)]   * bs[p & 7];
        } else if (t >= O3) {
            int q = t - O3;
            r = a[t] + bs[t]
              + a[q >> 6]          * bs[O2 + (q & 63)]
              + a[O2 + (q >> 3)]   * bs[q & 7];
        } else if (t >= O2) {
            int p2 = t - O2;
            r = a[t] + bs[t] + a[p2 >> 3] * bs[p2 & 7];
        } else {
            r = a[t] + bs[t];
        }
        Op[t] = r;
    }
}

// ---------------------------------------------------------------------------
// Kernel 3: truncated log of group-like element, in place on g_bufB.
// log(1+s) = s - s^2/2 + s^3/3 - s^4/4.  p3 has only L3,L4; p4 only L4.
// ---------------------------------------------------------------------------
__global__ void __launch_bounds__(256) k_log()
{
    int blk = blockIdx.x;
    float* S = g_bufB + (size_t)blk * STRIDE;
    int tid = threadIdx.x;

    __shared__ float s[O4];       // s levels 1..3
    __shared__ float P2[4672];    // p2: L2 [0,64), L3 [64,576), L4 [576,4672)
    __shared__ float P3[4608];    // p3: L3 [0,512), L4 [512,4608)

    for (int t = tid; t < O4; t += 256) s[t] = S[t];
    __syncthreads();

    // p2 = s (x) s
    for (int p = tid; p < 4096; p += 256)
        P2[576 + p] = s[p >> 9] * s[O3 + (p & 511)]
                    + s[O2 + (p >> 6)] * s[O2 + (p & 63)]
                    + s[O3 + (p >> 3)] * s[p & 7];
    for (int q = tid; q < 512; q += 256)
        P2[64 + q] = s[q >> 6] * s[O2 + (q & 63)]
                   + s[O2 + (q >> 3)] * s[q & 7];
    if (tid < 64) P2[tid] = s[tid >> 3] * s[tid & 7];
    __syncthreads();

    // p3 = s (x) p2  (levels 3,4 only)
    for (int p = tid; p < 4096; p += 256)
        P3[512 + p] = s[p >> 9] * P2[64 + (p & 511)]
                    + s[O2 + (p >> 6)] * P2[p & 63];
    for (int q = tid; q < 512; q += 256)
        P3[q] = s[q >> 6] * P2[q & 63];
    __syncthreads();

    // result (L1 unchanged); p4_L4 = s1 (x) p3_L3 computed on the fly
    for (int p = tid; p < 4096; p += 256) {
        float p4 = s[p >> 9] * P3[p & 511];
        S[O4 + p] = S[O4 + p] - 0.5f * P2[576 + p]
                  + (1.0f / 3.0f) * P3[512 + p] - 0.25f * p4;
    }
    for (int q = tid; q < 512; q += 256)
        S[O3 + q] = s[O3 + q] - 0.5f * P2[64 + q] + (1.0f / 3.0f) * P3[q];
    if (tid < 64)
        S[O2 + tid] = s[O2 + tid] - 0.5f * P2[tid];
}

// ---------------------------------------------------------------------------
// Kernel 4: mean over chunk dim -> pooled (B, SIZE)
// ---------------------------------------------------------------------------
__global__ void __launch_bounds__(256) k_pool()
{
    int g = blockIdx.x * 256 + threadIdx.x;
    if (g >= BB * SIZE) return;
    int b = g / SIZE, i = g - b * SIZE;
    const float* p = g_bufB + (size_t)b * NCH * STRIDE + i;
    float acc = 0.0f;
    #pragma unroll 8
    for (int n = 0; n < NCH; n++) acc += p[(size_t)n * STRIDE];
    g_pool[g] = acc * (1.0f / NCH);
}

// ---------------------------------------------------------------------------
// MLP
// ---------------------------------------------------------------------------
__global__ void k_zero_h()
{
    g_h[blockIdx.x * 256 + threadIdx.x] = 0.0f;   // grid 8 x 256
}

// grid (BB, 8): each block handles a 585-row slice of W1 for one batch element
__global__ void __launch_bounds__(256) k_gemv1(const float* __restrict__ W1)
{
    int b = blockIdx.x, sl = blockIdx.y;
    int j = threadIdx.x;
    int i0 = sl * 585;
    int i1 = i0 + 585; if (i1 > SIZE) i1 = SIZE;
    const float* pv = g_pool + b * SIZE;
    float acc = 0.0f;
    #pragma unroll 4
    for (int i = i0; i < i1; i++)
        acc = fmaf(__ldg(&pv[i]), __ldg(&W1[(size_t)i * HDIM + j]), acc);
    atomicAdd(&g_h[b * HDIM + j], acc);
}

__global__ void __launch_bounds__(256) k_out(const float* __restrict__ b1,
                                             const float* __restrict__ W2,
                                             const float* __restrict__ b2,
                                             float* __restrict__ out)
{
    int b = blockIdx.x, j = threadIdx.x;
    float v = fmaxf(g_h[b * HDIM + j] + b1[j], 0.0f) * W2[j];
    __shared__ float red[256];
    red[j] = v; __syncthreads();
    for (int s2 = 128; s2 > 0; s2 >>= 1) {
        if (j < s2) red[j] += red[j + s2];
        __syncthreads();
    }
    if (j == 0) out[b] = red[0] + b2[0];
}

// ---------------------------------------------------------------------------
extern "C" void kernel_launch(void* const* d_in, const int* in_sizes, int n_in,
                              void* d_out, int out_size)
{
    const float* x  = (const float*)d_in[0];
    const float* W1 = (const float*)d_in[1];
    const float* b1 = (const float*)d_in[2];
    const float* W2 = (const float*)d_in[3];
    const float* b2 = (const float*)d_in[4];
    float* out = (float*)d_out;

    (void)in_sizes; (void)n_in; (void)out_size;

    const int NB = BB * NCH;   // 1024

    // 1. per-chunk signatures -> g_bufA
    k_chunksig<<<NB, 256>>>(x);

    // 2. Hillis-Steele group-product scan over chunks (7 rounds, ping-pong)
    int dir = 0;
    for (int d = 1; d < NCH; d <<= 1) {
        k_scan<<<NB, 256>>>(d, dir);
        dir ^= 1;
    }
    // 7 rounds: final result in g_bufB (dir ended at 1 -> last wrote B? rounds:
    // d=1 A->B, d=2 B->A, d=4 A->B, d=8 B->A, d=16 A->B, d=32 B->A, d=64 A->B)
    // => final prefixes live in g_bufB.

    // 3. truncated log in place on g_bufB
    k_log<<<NB, 256>>>();

    // 4. mean pool over chunks
    k_pool<<<(BB * SIZE + 255) / 256, 256>>>();

    // 5. MLP
    k_zero_h<<<BB, 256>>>();
    dim3 g1(BB, 8);
    k_gemv1<<<g1, 256>>>(W1);
    k_out<<<BB, 256>>>(b1, W2, b2, out);
}

// round 2
// speedup vs baseline: 1.2198x; 1.2198x over previous
#include <cuda_runtime.h>

// Problem constants
#define BB    8
#define TT    2048
#define CIN   7
#define CC    8
#define NCH   128      // chunks per batch
#define CHK   16       // steps per chunk
#define NSEG  8        // segments per batch (NCH / CHK)
#define SIZE  4680     // 8 + 64 + 512 + 4096
#define STRIDE 4736    // padded row stride (floats)
#define O2    8
#define O3    72
#define O4    584
#define HDIM  256

// Scratch (device globals -- no runtime allocation)
__device__ float g_bufA[(size_t)BB * NCH * STRIDE];   // chunk sigs, later logs
__device__ float g_bufB[(size_t)BB * NCH * STRIDE];   // local prefixes
__device__ float g_off[(size_t)BB * NSEG * STRIDE];   // segment offsets (s=1..7 used)
__device__ float g_pool[BB * SIZE];
__device__ float g_h[BB * HDIM];

// ---------------------------------------------------------------------------
// In-place group product: c (smem, levels 1..4 flat) = c (x) B (global row).
// bl: smem scratch (O4 floats) for B's levels 1..3.  512 threads assumed.
// Top-down: L4 uses old L1..L3 of c, then L3, L2, L1.
// ---------------------------------------------------------------------------
__device__ __forceinline__ void ta_mul_acc(float* c, const float* __restrict__ Brow,
                                           float* bl, int tid)
{
    __syncthreads();
    for (int t = tid; t < O4; t += 512) bl[t] = Brow[t];
    __syncthreads();
    #pragma unroll
    for (int p = tid; p < 4096; p += 512)
        c[O4 + p] += Brow[O4 + p]
                   + c[p >> 9]        * bl[O3 + (p & 511)]
                   + c[O2 + (p >> 6)] * bl[O2 + (p & 63)]
                   + c[O3 + (p >> 3)] * bl[p & 7];
    __syncthreads();
    if (tid < 512) {
        int q = tid;
        c[O3 + q] += bl[O3 + q]
                   + c[q >> 6]        * bl[O2 + (q & 63)]
                   + c[O2 + (q >> 3)] * bl[q & 7];
    }
    __syncthreads();
    if (tid < 64) c[O2 + tid] += bl[O2 + tid] + c[tid >> 3] * bl[tid & 7];
    __syncthreads();
    if (tid < 8)  c[tid] += bl[tid];
    __syncthreads();
}

// ---------------------------------------------------------------------------
// Kernel 1: per-chunk signature via Chen iteration of exp(d_s) factors.
// ---------------------------------------------------------------------------
__global__ void __launch_bounds__(256) k_chunksig(const float* __restrict__ x)
{
    int blk = blockIdx.x;          // b*NCH + n
    int b = blk >> 7, n = blk & 127;
    int tid = threadIdx.x;

    __shared__ float d[CHK][CC];
    __shared__ float c[SIZE];

    if (tid < CHK * CC) {
        int s = tid >> 3, ch = tid & 7;
        int t = n * CHK + s;
        float v;
        if (ch < CIN) {
            float cur  = x[(b * TT + t) * CIN + ch];
            float prev = (t > 0) ? x[(b * TT + t - 1) * CIN + ch] : 0.0f;
            v = cur - prev;
        } else {
            v = (t > 0) ? (1.0f / 2047.0f) : 0.0f;
        }
        d[s][ch] = v;
    }
    __syncthreads();

    // init carry = exp_l1(d[0])
    for (int p = tid; p < 4096; p += 256) {
        int i = p >> 9, j = (p >> 6) & 7, k = (p >> 3) & 7, l = p & 7;
        c[O4 + p] = d[0][i] * d[0][j] * d[0][k] * d[0][l] * (1.0f / 24.0f);
    }
    for (int q = tid; q < 512; q += 256) {
        int i = q >> 6, j = (q >> 3) & 7, k = q & 7;
        c[O3 + q] = d[0][i] * d[0][j] * d[0][k] * (1.0f / 6.0f);
    }
    if (tid < 64) { int i = tid >> 3, j = tid & 7; c[O2 + tid] = d[0][i] * d[0][j] * 0.5f; }
    if (tid < 8)  c[tid] = d[0][tid];

    for (int s = 1; s < CHK; s++) {
        __syncthreads();
        for (int p = tid; p < 4096; p += 256) {
            int i = p >> 9, j = (p >> 6) & 7, k = (p >> 3) & 7, l = p & 7;
            float dl = d[s][l];
            float dkl = d[s][k] * dl;
            float djkl = d[s][j] * dkl;
            float dijkl = d[s][i] * djkl;
            c[O4 + p] += c[O3 + (p >> 3)] * dl
                       + c[O2 + (p >> 6)] * (dkl * 0.5f)
                       + c[p >> 9]        * (djkl * (1.0f / 6.0f))
                       + dijkl * (1.0f / 24.0f);
        }
        __syncthreads();
        for (int q = tid; q < 512; q += 256) {
            int i = q >> 6, j = (q >> 3) & 7, k = q & 7;
            float dk = d[s][k];
            float djk = d[s][j] * dk;
            float dijk = d[s][i] * djk;
            c[O3 + q] += c[O2 + (q >> 3)] * dk
                       + c[q >> 6] * (djk * 0.5f)
                       + dijk * (1.0f / 6.0f);
        }
        __syncthreads();
        if (tid < 64) {
            int i = tid >> 3, j = tid & 7;
            c[O2 + tid] += c[i] * d[s][j] + d[s][i] * d[s][j] * 0.5f;
        }
        __syncthreads();
        if (tid < 8) c[tid] += d[s][tid];
    }
    __syncthreads();

    float* o = g_bufA + (size_t)blk * STRIDE;
    for (int t = tid; t < SIZE; t += 256) o[t] = c[t];
}

// ---------------------------------------------------------------------------
// Kernel 2: serial local prefix product within each 16-chunk segment.
// grid = BB * NSEG = 64 blocks.
// ---------------------------------------------------------------------------
__global__ void __launch_bounds__(512) k_segscan()
{
    int blk = blockIdx.x;                 // b*NSEG + seg
    int tid = threadIdx.x;
    __shared__ float c[SIZE];
    __shared__ float bl[O4];

    size_t base = (size_t)blk * CHK * STRIDE;   // row b*NCH + seg*CHK
    const float* s0 = g_bufA + base;
    for (int t = tid; t < SIZE; t += 512) { float v = s0[t]; c[t] = v; g_bufB[base + t] = v; }

    for (int ci = 1; ci < CHK; ci++) {
        const float* Bp = g_bufA + base + (size_t)ci * STRIDE;
        ta_mul_acc(c, Bp, bl, tid);
        float* Op = g_bufB + base + (size_t)ci * STRIDE;
        for (int t = tid; t < SIZE; t += 512) Op[t] = c[t];
    }
}

// ---------------------------------------------------------------------------
// Kernel 3: exclusive scan of segment totals -> offsets. grid = BB blocks.
// off[s] = total[0] (x) ... (x) total[s-1],  s = 1..NSEG-1
// total[s] = local prefix at chunk s*CHK + CHK-1.
// ---------------------------------------------------------------------------
__global__ void __launch_bounds__(512) k_offsets()
{
    int b = blockIdx.x;
    int tid = threadIdx.x;
    __shared__ float c[SIZE];
    __shared__ float bl[O4];

    const float* t0 = g_bufB + ((size_t)(b * NCH + CHK - 1)) * STRIDE;
    float* off1 = g_off + (size_t)(b * NSEG + 1) * STRIDE;
    for (int t = tid; t < SIZE; t += 512) { float v = t0[t]; c[t] = v; off1[t] = v; }

    for (int s = 2; s < NSEG; s++) {
        const float* tot = g_bufB + ((size_t)(b * NCH + (s - 1) * CHK + CHK - 1)) * STRIDE;
        ta_mul_acc(c, tot, bl, tid);
        float* offs = g_off + (size_t)(b * NSEG + s) * STRIDE;
        for (int t = tid; t < SIZE; t += 512) offs[t] = c[t];
    }
}

// ---------------------------------------------------------------------------
// Kernel 4: fused apply (offset (x) local) + truncated log -> g_bufA.
// grid = BB * NCH = 1024 blocks, 256 threads.
// ---------------------------------------------------------------------------
__global__ void __launch_bounds__(256) k_apply_log()
{
    int blk = blockIdx.x;                 // b*NCH + n
    int b = blk >> 7, n = blk & 127;
    int seg = n >> 4;
    int tid = threadIdx.x;

    __shared__ float a[O4];       // offset levels 1..3
    __shared__ float bs[O4];      // local levels 1..3
    __shared__ float s[O4];       // merged levels 1..3
    __shared__ float P2[4672];    // p2: L2 [0,64), L3 [64,576), L4 [576,4672)
    __shared__ float P3[4608];    // p3: L3 [0,512), L4 [512,4608)

    const float* L = g_bufB + (size_t)blk * STRIDE;
    float r4[16];                 // merged level-4, p = tid + 256*m

    if (seg == 0) {
        for (int t = tid; t < O4; t += 256) s[t] = L[t];
        #pragma unroll
        for (int m = 0; m < 16; m++) r4[m] = L[O4 + tid + 256 * m];
    } else {
        const float* A = g_off + (size_t)(b * NSEG + seg) * STRIDE;
        for (int t = tid; t < O4; t += 256) { a[t] = A[t]; bs[t] = L[t]; }
        __syncthreads();
        // merged levels 1..3 into s
        for (int t = tid; t < O4; t += 256) {
            float r;
            if (t >= O3) {
                int q = t - O3;
                r = a[t] + bs[t]
                  + a[q >> 6]        * bs[O2 + (q & 63)]
                  + a[O2 + (q >> 3)] * bs[q & 7];
            } else if (t >= O2) {
                int p2i = t - O2;
                r = a[t] + bs[t] + a[p2i >> 3] * bs[p2i & 7];
            } else {
                r = a[t] + bs[t];
            }
            s[t] = r;
        }
        // merged level-4 in registers
        #pragma unroll
        for (int m = 0; m < 16; m++) {
            int p = tid + 256 * m;
            r4[m] = A[O4 + p] + L[O4 + p]
                  + a[p >> 9]        * bs[O3 + (p & 511)]
                  + a[O2 + (p >> 6)] * bs[O2 + (p & 63)]
                  + a[O3 + (p >> 3)] * bs[p & 7];
        }
    }
    __syncthreads();

    // --- truncated log of (1 + s), with s level-4 held in r4 ---
    // p2 = s (x) s
    for (int p = tid; p < 4096; p += 256)
        P2[576 + p] = s[p >> 9] * s[O3 + (p & 511)]
                    + s[O2 + (p >> 6)] * s[O2 + (p & 63)]
                    + s[O3 + (p >> 3)] * s[p & 7];
    for (int q = tid; q < 512; q += 256)
        P2[64 + q] = s[q >> 6] * s[O2 + (q & 63)]
                   + s[O2 + (q >> 3)] * s[q & 7];
    if (tid < 64) P2[tid] = s[tid >> 3] * s[tid & 7];
    __syncthreads();

    // p3 = s (x) p2 (levels 3,4 only)
    for (int p = tid; p < 4096; p += 256)
        P3[512 + p] = s[p >> 9] * P2[64 + (p & 511)]
                    + s[O2 + (p >> 6)] * P2[p & 63];
    for (int q = tid; q < 512; q += 256)
        P3[q] = s[q >> 6] * P2[q & 63];
    __syncthreads();

    float* S = g_bufA + (size_t)blk * STRIDE;
    #pragma unroll
    for (int m = 0; m < 16; m++) {
        int p = tid + 256 * m;
        float p4 = s[p >> 9] * P3[p & 511];
        S[O4 + p] = r4[m] - 0.5f * P2[576 + p]
                  + (1.0f / 3.0f) * P3[512 + p] - 0.25f * p4;
    }
    for (int q = tid; q < 512; q += 256)
        S[O3 + q] = s[O3 + q] - 0.5f * P2[64 + q] + (1.0f / 3.0f) * P3[q];
    if (tid < 64)
        S[O2 + tid] = s[O2 + tid] - 0.5f * P2[tid];
    if (tid < 8)
        S[tid] = s[tid];
}

// ---------------------------------------------------------------------------
// Kernel 5: mean over chunk dim -> pooled (B, SIZE)
// ---------------------------------------------------------------------------
__global__ void __launch_bounds__(256) k_pool()
{
    int g = blockIdx.x * 256 + threadIdx.x;
    if (g >= BB * SIZE) return;
    int b = g / SIZE, i = g - b * SIZE;
    const float* p = g_bufA + (size_t)b * NCH * STRIDE + i;
    float acc = 0.0f;
    #pragma unroll 8
    for (int n = 0; n < NCH; n++) acc += p[(size_t)n * STRIDE];
    g_pool[g] = acc * (1.0f / NCH);
}

// ---------------------------------------------------------------------------
// MLP
// ---------------------------------------------------------------------------
__global__ void k_zero_h()
{
    g_h[blockIdx.x * 256 + threadIdx.x] = 0.0f;   // grid 8 x 256
}

// grid (BB, 16): each block handles a 293-row slice of W1 for one batch element
__global__ void __launch_bounds__(256) k_gemv1(const float* __restrict__ W1)
{
    int b = blockIdx.x, sl = blockIdx.y;
    int j = threadIdx.x;
    int i0 = sl * 293;
    int i1 = i0 + 293; if (i1 > SIZE) i1 = SIZE;
    const float* pv = g_pool + b * SIZE;
    float acc = 0.0f;
    #pragma unroll 4
    for (int i = i0; i < i1; i++)
        acc = fmaf(__ldg(&pv[i]), __ldg(&W1[(size_t)i * HDIM + j]), acc);
    atomicAdd(&g_h[b * HDIM + j], acc);
}

__global__ void __launch_bounds__(256) k_out(const float* __restrict__ b1,
                                             const float* __restrict__ W2,
                                             const float* __restrict__ b2,
                                             float* __restrict__ out)
{
    int b = blockIdx.x, j = threadIdx.x;
    float v = fmaxf(g_h[b * HDIM + j] + b1[j], 0.0f) * W2[j];
    __shared__ float red[256];
    red[j] = v; __syncthreads();
    for (int s2 = 128; s2 > 0; s2 >>= 1) {
        if (j < s2) red[j] += red[j + s2];
        __syncthreads();
    }
    if (j == 0) out[b] = red[0] + b2[0];
}

// ---------------------------------------------------------------------------
extern "C" void kernel_launch(void* const* d_in, const int* in_sizes, int n_in,
                              void* d_out, int out_size)
{
    const float* x  = (const float*)d_in[0];
    const float* W1 = (const float*)d_in[1];
    const float* b1 = (const float*)d_in[2];
    const float* W2 = (const float*)d_in[3];
    const float* b2 = (const float*)d_in[4];
    float* out = (float*)d_out;

    (void)in_sizes; (void)n_in; (void)out_size;

    // 1. per-chunk signatures -> g_bufA
    k_chunksig<<<BB * NCH, 256>>>(x);

    // 2. segmented scan: local prefixes -> g_bufB
    k_segscan<<<BB * NSEG, 512>>>();

    // 3. segment offsets -> g_off
    k_offsets<<<BB, 512>>>();

    // 4. apply offsets + truncated log -> g_bufA
    k_apply_log<<<BB * NCH, 256>>>();

    // 5. mean pool over chunks
    k_pool<<<(BB * SIZE + 255) / 256, 256>>>();

    // 6. MLP
    k_zero_h<<<BB, 256>>>();
    dim3 g1(BB, 16);
    k_gemv1<<<g1, 256>>>(W1);
    k_out<<<BB, 256>>>(b1, W2, b2, out);
}

// round 3
// speedup vs baseline: 1.4996x; 1.2294x over previous
#include <cuda_runtime.h>

// Problem constants
#define BB    8
#define TT    2048
#define CIN   7
#define CC    8
#define NCH   128      // chunks per batch
#define CHK   16       // steps per chunk
#define NSEG  8        // segments per batch (NCH / CHK)
#define SIZE  4680     // 8 + 64 + 512 + 4096
#define STRIDE 4736    // padded row stride (floats)
#define O2    8
#define O3    72
#define O4    584
#define HDIM  256

// Scratch (device globals -- no runtime allocation)
__device__ float g_bufA[(size_t)BB * NCH * STRIDE];   // chunk sigs, later logs
__device__ float g_bufB[(size_t)BB * NCH * STRIDE];   // local prefixes
__device__ float g_off[(size_t)BB * NSEG * STRIDE];   // segment offsets (s=1..7 used)
__device__ float g_pool[BB * SIZE];
__device__ float g_h[BB * HDIM];

// ---------------------------------------------------------------------------
// Kernel 1: per-chunk signature via Chen iteration of exp(d_s) factors.
// Level-4 carry lives in registers (16/thread); smem carry = levels 1..3 only.
// 2 syncthreads per step (read phase -> write phase).
// ---------------------------------------------------------------------------
__global__ void __launch_bounds__(256) k_chunksig(const float* __restrict__ x)
{
    int blk = blockIdx.x;          // b*NCH + n
    int b = blk >> 7, n = blk & 127;
    int tid = threadIdx.x;

    __shared__ float d[CHK][CC];
    __shared__ float c[O4];        // levels 1..3 of carry

    if (tid < CHK * CC) {
        int s = tid >> 3, ch = tid & 7;
        int t = n * CHK + s;
        float v;
        if (ch < CIN) {
            float cur  = x[(b * TT + t) * CIN + ch];
            float prev = (t > 0) ? x[(b * TT + t - 1) * CIN + ch] : 0.0f;
            v = cur - prev;
        } else {
            v = (t > 0) ? (1.0f / 2047.0f) : 0.0f;
        }
        d[s][ch] = v;
    }
    __syncthreads();

    // For L4 element p = tid + 256*m:
    //   p&7 = tid&7 (=l), (p>>3)&7 = (tid>>3)&7 (=k), (p>>6)&7 = j0 + 4*(m&1),
    //   p>>9 = m>>1, p>>3 = (tid>>3)+32m, p>>6 = (tid>>6)+4m.
    const int l = tid & 7, k = (tid >> 3) & 7, j0 = tid >> 6;   // j0 in 0..3
    float r4[16];

    // ---- init carry = exp_l1(d[0]) ----
    {
        float d8[8];
        #pragma unroll
        for (int i = 0; i < 8; i++) d8[i] = d[0][i];
        float dl = d8[l], dk = d8[k], dkl = dk * dl;
        float dje = d8[j0], djo = d8[j0 + 4];
        #pragma unroll
        for (int m = 0; m < 16; m++) {
            float dj = (m & 1) ? djo : dje;
            r4[m] = d8[m >> 1] * dj * dkl * (1.0f / 24.0f);
        }
        c[O3 + tid]       = dje * dkl * (1.0f / 6.0f);
        c[O3 + tid + 256] = djo * dkl * (1.0f / 6.0f);
        if (tid < 64) c[O2 + tid] = d8[tid >> 3] * d8[tid & 7] * 0.5f;
        if (tid < 8)  c[tid] = d8[tid];
    }

    for (int s = 1; s < CHK; s++) {
        __syncthreads();
        // ---- read phase ----
        float d8[8], c1r[8];
        #pragma unroll
        for (int i = 0; i < 8; i++) d8[i] = d[s][i];
        #pragma unroll
        for (int i = 0; i < 8; i++) c1r[i] = c[i];
        float dl = d8[l], dk = d8[k], dkl = dk * dl;
        float dje = d8[j0], djo = d8[j0 + 4];
        float djkle = dje * dkl, djklo = djo * dkl;
        float hdkl = 0.5f * dkl;
        #pragma unroll
        for (int m = 0; m < 16; m++) {
            float c3 = c[O3 + (tid >> 3) + 32 * m];
            float c2 = c[O2 + (tid >> 6) + 4 * m];
            float djkl = (m & 1) ? djklo : djkle;
            r4[m] += c3 * dl + c2 * hdkl
                   + c1r[m >> 1] * ((1.0f / 6.0f) * djkl)
                   + d8[m >> 1] * djkl * (1.0f / 24.0f);
        }
        float cO3a = c[O3 + tid], cO3b = c[O3 + tid + 256];
        float c2qa = c[O2 + (tid >> 3)], c2qb = c[O2 + (tid >> 3) + 32];
        float t3a = cO3a + c2qa * dl + c1r[j0]     * hdkl + djkle * (1.0f / 6.0f);
        float t3b = cO3b + c2qb * dl + c1r[j0 + 4] * hdkl + djklo * (1.0f / 6.0f);
        float t2 = 0.0f, t1 = 0.0f;
        if (tid < 64) t2 = c[O2 + tid] + c1r[tid >> 3] * d8[tid & 7]
                         + d8[tid >> 3] * d8[tid & 7] * 0.5f;
        if (tid < 8)  t1 = c1r[tid] + d8[tid];
        __syncthreads();
        // ---- write phase ----
        c[O3 + tid] = t3a; c[O3 + tid + 256] = t3b;
        if (tid < 64) c[O2 + tid] = t2;
        if (tid < 8)  c[tid] = t1;
    }
    __syncthreads();

    float* o = g_bufA + (size_t)blk * STRIDE;
    for (int t = tid; t < O4; t += 256) o[t] = c[t];
    #pragma unroll
    for (int m = 0; m < 16; m++) o[O4 + tid + 256 * m] = r4[m];
}

// ---------------------------------------------------------------------------
// Kernel 2: serial local prefix product within each 16-chunk segment.
// grid = 64 blocks, 512 threads. Carry L4 in regs (8/thread); B lows
// double-buffered in smem; 2 syncs per product.
// For p = tid + 512*m (512 threads): p&7, p&63 fixed; p&511 = tid;
// p>>9 = m; p>>3 = (tid>>3)+64m; p>>6 = (tid>>6)+8m.
// ---------------------------------------------------------------------------
__global__ void __launch_bounds__(512) k_segscan()
{
    int blk = blockIdx.x;                 // b*NSEG + seg
    int tid = threadIdx.x;
    __shared__ float c[O4];
    __shared__ float bl[2][O4];

    size_t base = (size_t)blk * CHK * STRIDE;
    const float* A0 = g_bufA + base;
    float* Out = g_bufB + base;

    float r4[8];
    for (int t = tid; t < O4; t += 512) { float v = A0[t]; c[t] = v; Out[t] = v; }
    #pragma unroll
    for (int m = 0; m < 8; m++) {
        float v = A0[O4 + tid + 512 * m];
        r4[m] = v; Out[O4 + tid + 512 * m] = v;
    }
    // preload lows of chunk 1
    {
        const float* A1 = A0 + STRIDE;
        for (int t = tid; t < O4; t += 512) bl[0][t] = A1[t];
    }

    for (int ci = 1; ci < CHK; ci++) {
        int cur = (ci - 1) & 1, nxt = ci & 1;
        __syncthreads();   // prev writes + bl[cur] ready
        if (ci + 1 < CHK) {
            const float* An = A0 + (size_t)(ci + 1) * STRIDE;
            for (int t = tid; t < O4; t += 512) bl[nxt][t] = An[t];
        }
        const float* Bg = A0 + (size_t)ci * STRIDE;
        const float* bb = bl[cur];
        float b1f = bb[tid & 7], b2f = bb[O2 + (tid & 63)], b3f = bb[O3 + tid];
        float c1r[8];
        #pragma unroll
        for (int i = 0; i < 8; i++) c1r[i] = c[i];
        #pragma unroll
        for (int m = 0; m < 8; m++) {
            int p = tid + 512 * m;
            r4[m] += Bg[O4 + p]
                   + c1r[m] * b3f
                   + c[O2 + (tid >> 6) + 8 * m] * b2f
                   + c[O3 + (tid >> 3) + 64 * m] * b1f;
        }
        float t3 = c[O3 + tid] + b3f + c1r[tid >> 6] * b2f + c[O2 + (tid >> 3)] * b1f;
        float t2 = 0.0f, t1 = 0.0f;
        if (tid < 64) t2 = c[O2 + tid] + bb[O2 + tid] + c1r[tid >> 3] * bb[tid & 7];
        if (tid < 8)  t1 = c1r[tid] + bb[tid];
        __syncthreads();
        c[O3 + tid] = t3;
        if (tid < 64) c[O2 + tid] = t2;
        if (tid < 8)  c[tid] = t1;
        float* Op = Out + (size_t)ci * STRIDE;
        Op[O3 + tid] = t3;
        if (tid < 64) Op[O2 + tid] = t2;
        if (tid < 8)  Op[tid] = t1;
        #pragma unroll
        for (int m = 0; m < 8; m++) Op[O4 + tid + 512 * m] = r4[m];
    }
}

// ---------------------------------------------------------------------------
// Kernel 3: offsets, parallel over (b, s). grid = BB*(NSEG-1) = 56 blocks.
// Block (b,s) computes off[b][s] = T_0 (x) ... (x) T_{s-1} serially in smem.
// ---------------------------------------------------------------------------
__global__ void __launch_bounds__(512) k_offsets()
{
    int blk = blockIdx.x;
    int b = blk / 7, s = blk % 7 + 1;
    int tid = threadIdx.x;
    __shared__ float c[O4];
    __shared__ float bl[O4];

    const float* T0 = g_bufB + (size_t)(b * NCH + CHK - 1) * STRIDE;
    float r4[8];
    for (int t = tid; t < O4; t += 512) c[t] = T0[t];
    #pragma unroll
    for (int m = 0; m < 8; m++) r4[m] = T0[O4 + tid + 512 * m];

    for (int t = 1; t < s; t++) {
        const float* Tt = g_bufB + (size_t)(b * NCH + t * CHK + CHK - 1) * STRIDE;
        __syncthreads();   // prior bl reads / c writes done
        for (int u = tid; u < O4; u += 512) bl[u] = Tt[u];
        __syncthreads();   // bl + c ready
        float b1f = bl[tid & 7], b2f = bl[O2 + (tid & 63)], b3f = bl[O3 + tid];
        float c1r[8];
        #pragma unroll
        for (int i = 0; i < 8; i++) c1r[i] = c[i];
        #pragma unroll
        for (int m = 0; m < 8; m++) {
            r4[m] += Tt[O4 + tid + 512 * m]
                   + c1r[m] * b3f
                   + c[O2 + (tid >> 6) + 8 * m] * b2f
                   + c[O3 + (tid >> 3) + 64 * m] * b1f;
        }
        float t3 = c[O3 + tid] + b3f + c1r[tid >> 6] * b2f + c[O2 + (tid >> 3)] * b1f;
        float t2 = 0.0f, t1 = 0.0f;
        if (tid < 64) t2 = c[O2 + tid] + bl[O2 + tid] + c1r[tid >> 3] * bl[tid & 7];
        if (tid < 8)  t1 = c1r[tid] + bl[tid];
        __syncthreads();
        c[O3 + tid] = t3;
        if (tid < 64) c[O2 + tid] = t2;
        if (tid < 8)  c[tid] = t1;
    }
    __syncthreads();
    float* off = g_off + (size_t)(b * NSEG + s) * STRIDE;
    for (int t = tid; t < O4; t += 512) off[t] = c[t];
    #pragma unroll
    for (int m = 0; m < 8; m++) off[O4 + tid + 512 * m] = r4[m];
}

// ---------------------------------------------------------------------------
// Kernel 4: fused apply (offset (x) local) + truncated log -> g_bufA.
// Level-4 running accumulator in registers; p2/p3 level-4 never stored.
// smem ~11 KB. grid = 1024, 256 threads.
// ---------------------------------------------------------------------------
__global__ void __launch_bounds__(256) k_apply_log()
{
    int blk = blockIdx.x;                 // b*NCH + n
    int b = blk >> 7, n = blk & 127;
    int seg = n >> 4;
    int tid = threadIdx.x;

    __shared__ float s[O4];       // merged levels 1..3
    __shared__ float al[O4];      // offset lows
    __shared__ float blw[O4];     // local lows
    __shared__ float P2_2[64], P2_3[512], P3_3[512];

    const float* L = g_bufB + (size_t)blk * STRIDE;
    float r4[16];

    if (seg == 0) {
        for (int t = tid; t < O4; t += 256) s[t] = L[t];
        #pragma unroll
        for (int m = 0; m < 16; m++) r4[m] = L[O4 + tid + 256 * m];
    } else {
        const float* A = g_off + (size_t)(b * NSEG + seg) * STRIDE;
        for (int t = tid; t < O4; t += 256) { al[t] = A[t]; blw[t] = L[t]; }
        __syncthreads();
        for (int t = tid; t < O4; t += 256) {
            float r;
            if (t >= O3) {
                int q = t - O3;
                r = al[t] + blw[t]
                  + al[q >> 6]        * blw[O2 + (q & 63)]
                  + al[O2 + (q >> 3)] * blw[q & 7];
            } else if (t >= O2) {
                int u = t - O2;
                r = al[t] + blw[t] + al[u >> 3] * blw[u & 7];
            } else {
                r = al[t] + blw[t];
            }
            s[t] = r;
        }
        float a1r[8];
        #pragma unroll
        for (int i = 0; i < 8; i++) a1r[i] = al[i];
        float b3a = blw[O3 + tid], b3b = blw[O3 + tid + 256];
        float b2f = blw[O2 + (tid & 63)], b1f = blw[tid & 7];
        #pragma unroll
        for (int m = 0; m < 16; m++) {
            int p = tid + 256 * m;
            float b3v = (m & 1) ? b3b : b3a;
            r4[m] = A[O4 + p] + L[O4 + p]
                  + a1r[m >> 1] * b3v
                  + al[O2 + (tid >> 6) + 4 * m] * b2f
                  + al[O3 + (tid >> 3) + 32 * m] * b1f;
        }
    }
    __syncthreads();

    // ---- truncated log, folding into r4 ----
    float s1r[8];
    #pragma unroll
    for (int i = 0; i < 8; i++) s1r[i] = s[i];
    float s3a = s[O3 + tid], s3b = s[O3 + tid + 256];
    float s2f = s[O2 + (tid & 63)], s1f = s[tid & 7];

    // p2: fold -1/2 p2_L4; store p2 lows
    #pragma unroll
    for (int m = 0; m < 16; m++) {
        float s3v = (m & 1) ? s3b : s3a;
        float p2 = s1r[m >> 1] * s3v
                 + s[O2 + (tid >> 6) + 4 * m] * s2f
                 + s[O3 + (tid >> 3) + 32 * m] * s1f;
        r4[m] -= 0.5f * p2;
    }
    {
        float pa = s1r[tid >> 6] * s2f + s[O2 + (tid >> 3)] * s1f;
        float pb = s1r[(tid >> 6) + 4] * s2f + s[O2 + (tid >> 3) + 32] * s1f;
        P2_3[tid] = pa; P2_3[tid + 256] = pb;
    }
    if (tid < 64) P2_2[tid] = s1r[tid >> 3] * s[tid & 7];
    __syncthreads();

    // p3: fold +1/3 p3_L4; store p3 level 3
    {
        float P23a = P2_3[tid], P23b = P2_3[tid + 256];
        float P22f = P2_2[tid & 63];
        #pragma unroll
        for (int m = 0; m < 16; m++) {
            float pv = (m & 1) ? P23b : P23a;
            float p3 = s1r[m >> 1] * pv + s[O2 + (tid >> 6) + 4 * m] * P22f;
            r4[m] += (1.0f / 3.0f) * p3;
        }
        P3_3[tid]       = s1r[tid >> 6] * P22f;
        P3_3[tid + 256] = s1r[(tid >> 6) + 4] * P22f;
    }
    __syncthreads();

    // p4: fold -1/4 p4_L4; write out
    float* S = g_bufA + (size_t)blk * STRIDE;
    {
        float P33a = P3_3[tid], P33b = P3_3[tid + 256];
        #pragma unroll
        for (int m = 0; m < 16; m++) {
            float pv = (m & 1) ? P33b : P33a;
            r4[m] -= 0.25f * s1r[m >> 1] * pv;
            S[O4 + tid + 256 * m] = r4[m];
        }
        S[O3 + tid]       = s3a - 0.5f * P2_3[tid]       + (1.0f / 3.0f) * P33a;
        S[O3 + tid + 256] = s3b - 0.5f * P2_3[tid + 256] + (1.0f / 3.0f) * P33b;
    }
    if (tid < 64) S[O2 + tid] = s[O2 + tid] - 0.5f * P2_2[tid];
    if (tid < 8)  S[tid] = s1r[tid];
}

// ---------------------------------------------------------------------------
// Kernel 5: mean over chunk dim -> pooled (B, SIZE)
// ---------------------------------------------------------------------------
__global__ void __launch_bounds__(256) k_pool()
{
    int g = blockIdx.x * 256 + threadIdx.x;
    if (g >= BB * SIZE) return;
    int b = g / SIZE, i = g - b * SIZE;
    const float* p = g_bufA + (size_t)b * NCH * STRIDE + i;
    float acc = 0.0f;
    #pragma unroll 8
    for (int n = 0; n < NCH; n++) acc += p[(size_t)n * STRIDE];
    g_pool[g] = acc * (1.0f / NCH);
}

// ---------------------------------------------------------------------------
// MLP
// ---------------------------------------------------------------------------
__global__ void k_zero_h()
{
    g_h[blockIdx.x * 256 + threadIdx.x] = 0.0f;   // grid 8 x 256
}

__global__ void __launch_bounds__(256) k_gemv1(const float* __restrict__ W1)
{
    int b = blockIdx.x, sl = blockIdx.y;
    int j = threadIdx.x;
    int i0 = sl * 293;
    int i1 = i0 + 293; if (i1 > SIZE) i1 = SIZE;
    const float* pv = g_pool + b * SIZE;
    float acc = 0.0f;
    #pragma unroll 4
    for (int i = i0; i < i1; i++)
        acc = fmaf(__ldg(&pv[i]), __ldg(&W1[(size_t)i * HDIM + j]), acc);
    atomicAdd(&g_h[b * HDIM + j], acc);
}

__global__ void __launch_bounds__(256) k_out(const float* __restrict__ b1,
                                             const float* __restrict__ W2,
                                             const float* __restrict__ b2,
                                             float* __restrict__ out)
{
    int b = blockIdx.x, j = threadIdx.x;
    float v = fmaxf(g_h[b * HDIM + j] + b1[j], 0.0f) * W2[j];
    __shared__ float red[256];
    red[j] = v; __syncthreads();
    for (int s2 = 128; s2 > 0; s2 >>= 1) {
        if (j < s2) red[j] += red[j + s2];
        __syncthreads();
    }
    if (j == 0) out[b] = red[0] + b2[0];
}

// ---------------------------------------------------------------------------
extern "C" void kernel_launch(void* const* d_in, const int* in_sizes, int n_in,
                              void* d_out, int out_size)
{
    const float* x  = (const float*)d_in[0];
    const float* W1 = (const float*)d_in[1];
    const float* b1 = (const float*)d_in[2];
    const float* W2 = (const float*)d_in[3];
    const float* b2 = (const float*)d_in[4];
    float* out = (float*)d_out;

    (void)in_sizes; (void)n_in; (void)out_size;

    k_zero_h<<<BB, 256>>>();
    k_chunksig<<<BB * NCH, 256>>>(x);
    k_segscan<<<BB * NSEG, 512>>>();
    k_offsets<<<BB * (NSEG - 1), 512>>>();
    k_apply_log<<<BB * NCH, 256>>>();
    k_pool<<<(BB * SIZE + 255) / 256, 256>>>();
    dim3 g1(BB, 16);
    k_gemv1<<<g1, 256>>>(W1);
    k_out<<<BB, 256>>>(b1, W2, b2, out);
}